// round 5
// baseline (speedup 1.0000x reference)
#include <cuda_runtime.h>
#include <math.h>

// Problem constants (match reference)
#define N_INPUTSC 2048
#define UNITSC    2048
#define LC        8
#define FANINC    4096
#define TOTALC    18432

#define KC      128          // k-chunks (partial-sum depth)
#define KCH     32           // rows per chunk
#define JT      8            // column tiles
#define JPB     256          // cols per tile
#define NTILES  (KC * JT)    // 1024 tiles per layer
#define GEMV_BLOCKS 592      // 4 blocks/SM * 148 SMs

// Persistent scratch (allocation-free rule: __device__ globals)
__device__ float g_partial[2][KC * UNITSC];  // ping-pong partials, 1MB each
__device__ float g_outputs[TOTALC];          // materialized state vector
__device__ float g_gather[FANINC];           // gathered input for current layer
__device__ int   g_tile_ctr;                 // gemv work queue (reset by prep)

// Warp-shuffle reduce of one column of the previous layer's partials.
__device__ __forceinline__ float warp_reduce_col(const float* __restrict__ P,
                                                 int u, int lane) {
    float s = 0.f;
#pragma unroll
    for (int j = 0; j < 4; ++j)
        s += P[(lane + 32 * j) * UNITSC + u];
#pragma unroll
    for (int off = 16; off; off >>= 1)
        s += __shfl_xor_sync(0xffffffffu, s, off);
    return s;
}

// ---------------------------------------------------------------------------
// prep: one warp per element. Warps 0..2047 materialize slice `layer`
// (layer==LC: write final result to `out` instead); warps 2048..6143 build
// the gathered vector g_gather. Block 0 resets the gemv tile queue.
// ---------------------------------------------------------------------------
__global__ __launch_bounds__(256) void prep_kernel(
    int layer,
    const float* __restrict__ x,
    const int*   __restrict__ node_inds,
    const float* __restrict__ bs,
    float*       __restrict__ out)
{
    if (blockIdx.x == 0 && threadIdx.x == 0) g_tile_ctr = 0;

    int gtid = blockIdx.x * 256 + threadIdx.x;
    int wid  = gtid >> 5;
    int lane = gtid & 31;
    const float* Pprev = g_partial[(layer + 1) & 1];
    const float* bprev = bs + (layer - 1) * UNITSC;
    const int base  = layer << 11;
    const int limit = base + UNITSC;

    if (wid < UNITSC) {
        int u = wid;
        float o;
        if (layer == 0) {
            o = x[u];
        } else {
            o = tanhf(warp_reduce_col(Pprev, u, lane) + bprev[u]);
        }
        if (lane == 0) {
            if (layer == LC) out[u]             = o;
            else             g_outputs[base + u] = o;
        }
    } else {
        int k = wid - UNITSC;   // only launched when layer < LC
        int idx = node_inds[layer * FANINC + k];
        float v = 0.f;
        if (idx < base) {
            v = g_outputs[idx];           // older slice, already materialized
        } else if (idx < limit) {
            int u = idx - base;           // latest slice: recompute
            if (layer == 0) v = x[u];
            else            v = tanhf(warp_reduce_col(Pprev, u, lane) + bprev[u]);
        }
        if (lane == 0) g_gather[k] = v;
    }
}

// ---------------------------------------------------------------------------
// gemv: persistent W-streaming blocks with an atomic tile queue.
// Tile t -> (kc = t/8, jt = t%8): rows [kc*32, kc*32+32), cols [jt*256,+256).
// Thread: tx = tid&63 -> 4 cols (float4); tg = tid>>6 -> 8-row group.
// 8 independent LDG.128 per thread; 4 row-groups reduced through smem.
// ---------------------------------------------------------------------------
__global__ __launch_bounds__(256) void gemv_kernel(
    int layer,
    const float* __restrict__ Ws)
{
    float* Pcur = g_partial[layer & 1];
    const int tid = threadIdx.x;
    const int tx  = tid & 63;
    const int tg  = tid >> 6;

    __shared__ float  sg[KCH];
    __shared__ float4 red[3][64];
    __shared__ int    s_tile;

    const float* Wbase = Ws + (size_t)layer * FANINC * UNITSC;

    for (;;) {
        if (tid == 0) s_tile = atomicAdd(&g_tile_ctr, 1);
        __syncthreads();
        const int t = s_tile;
        if (t >= NTILES) break;

        const int kc = t >> 3;
        const int jt = t & 7;
        if (tid < KCH) sg[tid] = g_gather[kc * KCH + tid];
        __syncthreads();

        const int j0 = jt * JPB + tx * 4;
        const float* W = Wbase + ((size_t)(kc * KCH + tg * 8)) * UNITSC + j0;

        float ax = 0.f, ay = 0.f, az = 0.f, aw = 0.f;
#pragma unroll
        for (int r = 0; r < 8; ++r) {
            float gk = sg[tg * 8 + r];
            float4 w = *reinterpret_cast<const float4*>(W + (size_t)r * UNITSC);
            ax = fmaf(gk, w.x, ax);
            ay = fmaf(gk, w.y, ay);
            az = fmaf(gk, w.z, az);
            aw = fmaf(gk, w.w, aw);
        }

        if (tg > 0) red[tg - 1][tx] = make_float4(ax, ay, az, aw);
        __syncthreads();
        if (tg == 0) {
#pragma unroll
            for (int r = 0; r < 3; ++r) {
                float4 p = red[r][tx];
                ax += p.x; ay += p.y; az += p.z; aw += p.w;
            }
            *reinterpret_cast<float4*>(Pcur + kc * UNITSC + j0) =
                make_float4(ax, ay, az, aw);
        }
        __syncthreads();   // protect sg/red/s_tile before next iteration
    }
}

extern "C" void kernel_launch(void* const* d_in, const int* in_sizes, int n_in,
                              void* d_out, int out_size) {
    const float* x  = (const float*)d_in[0];   // [2048] f32
    const int*   ni = (const int*)d_in[1];     // [8, 4096] i32
    const float* Ws = (const float*)d_in[2];   // [8, 4096, 2048] f32
    const float* bs = (const float*)d_in[3];   // [8, 2048] f32
    float* out = (float*)d_out;                // [2048] f32

    for (int i = 0; i < LC; ++i) {
        prep_kernel<<<(UNITSC + FANINC) / 8, 256>>>(i, x, ni, bs, out);
        gemv_kernel<<<GEMV_BLOCKS, 256>>>(i, Ws);
    }
    // Final "prep": materialize layer-8 output straight into d_out.
    prep_kernel<<<UNITSC / 8, 256>>>(LC, x, ni, bs, out);
}